// round 4
// baseline (speedup 1.0000x reference)
#include <cuda_runtime.h>

#define SSCALE 1.6666666666666667f

__device__ __forceinline__ float ssilu(float x) {
    float e = __expf(-x);
    return SSCALE * __fdividef(x, 1.0f + e);
}

// ---- packed f32x2 helpers (Blackwell FFMA2) ----
__device__ __forceinline__ unsigned long long dup2(float x) {
    unsigned long long r;
    asm("mov.b64 %0, {%1, %1};" : "=l"(r) : "f"(x));
    return r;
}
__device__ __forceinline__ unsigned long long pk2(float x, float y) {
    unsigned long long r;
    asm("mov.b64 %0, {%1, %2};" : "=l"(r) : "f"(x), "f"(y));
    return r;
}
__device__ __forceinline__ void up2(float& x, float& y, unsigned long long v) {
    asm("mov.b64 {%0, %1}, %2;" : "=f"(x), "=f"(y) : "l"(v));
}
#define FMA2(d, a, b) asm("fma.rn.f32x2 %0, %1, %2, %0;" : "+l"(d) : "l"(a), "l"(b))
#define MUL2(d, a, b) asm("mul.rn.f32x2 %0, %1, %2;" : "=l"(d) : "l"(a), "l"(b))

#define E_MAX 700000
#define N_MAX 40000

__device__ __align__(16) float g_xdown[(size_t)E_MAX * 16];
__device__ __align__(16) float g_xe[(size_t)E_MAX * 16];
__device__ __align__(16) float g_h[(size_t)N_MAX * 128];

// ---------------- K0: zero scratch ----------------
__global__ void k_zero(int n_xe4, int n_h4) {
    int i = blockIdx.x * blockDim.x + threadIdx.x;
    int stride = gridDim.x * blockDim.x;
    float4 z = make_float4(0.f, 0.f, 0.f, 0.f);
    for (int r = i; r < n_xe4; r += stride) ((float4*)g_xe)[r] = z;
    for (int r = i; r < n_h4; r += stride) ((float4*)g_h)[r] = z;
}

// ---------------- K1: edge dense + down projection (512 threads) ---------
// x_ba = ssilu(m @ W_ba) * (rbf @ W_rbf);  g_xdown = x_ba @ W_down
// 64 edges/tile, 512 threads = 16 warps.
// Warp w: edges eb = (w&7)*8 (4 pairs), cols cb = (w>>3)*64; lane: 2 cols.
__global__ __launch_bounds__(512, 1) void k_edge_down(
    const float* __restrict__ m, const float* __restrict__ rbf,
    const float* __restrict__ Wba, const float* __restrict__ Wrbf,
    const float* __restrict__ Wdown, int E)
{
    extern __shared__ float sm_[];
    float* sWba  = sm_;               // [128][128] fp32 (k-major)
    float* sWrbf = sWba + 16384;      // [16][128]
    float* sWd   = sWrbf + 2048;      // [128][16] natural
    float* sMT   = sWd + 2048;        // [128][64]  m transposed [k][e]
    float* sRbfT = sMT + 8192;        // [16][64]   rbf transposed [s][e]
    float* sXT   = sMT;               // [128][66]  x_ba transposed (aliases sMT+sRbfT)

    int tid = threadIdx.x;
    for (int i = tid; i < 16384; i += 512) sWba[i] = Wba[i];
    for (int i = tid; i < 2048; i += 512) sWrbf[i] = Wrbf[i];
    for (int i = tid; i < 2048; i += 512) sWd[i] = Wdown[i];

    int lane = tid & 31, w = tid >> 5;
    int eb = (w & 7) * 8;
    int jb = (w >> 3) * 64 + lane * 2;
    int pd_p = tid >> 4;          // down-proj pair id 0..31
    int pd_d = tid & 15;          // down-proj d 0..15
    int ntiles = (E + 63) >> 6;

    for (int tile = blockIdx.x; tile < ntiles; tile += gridDim.x) {
        int e0 = tile << 6;
        __syncthreads();   // prev tile's down-proj reads done (and weights on iter 0)

        // load m tile transposed [k][e]
        #pragma unroll
        for (int it = 0; it < 4; it++) {
            int r = tid + it * 512;
            int e = r >> 5, c = r & 31;
            float4 v = make_float4(0.f, 0.f, 0.f, 0.f);
            if (e0 + e < E) v = *(const float4*)(m + (size_t)(e0 + e) * 128 + c * 4);
            sMT[(c * 4 + 0) * 64 + e] = v.x;
            sMT[(c * 4 + 1) * 64 + e] = v.y;
            sMT[(c * 4 + 2) * 64 + e] = v.z;
            sMT[(c * 4 + 3) * 64 + e] = v.w;
        }
        // load rbf tile transposed [s][e]
        {
            int e = tid & 63, sq = tid >> 6;   // sq 0..7
            float2 v = make_float2(0.f, 0.f);
            if (e0 + e < E) v = *(const float2*)(rbf + (size_t)(e0 + e) * 16 + sq * 2);
            sRbfT[(sq * 2 + 0) * 64 + e] = v.x;
            sRbfT[(sq * 2 + 1) * 64 + e] = v.y;
        }
        __syncthreads();

        // main mma: acc[p][c] packs edges (eb+2p, eb+2p+1) for col jb+c
        unsigned long long acc[4][2];
        #pragma unroll
        for (int p = 0; p < 4; p++) { acc[p][0] = 0ull; acc[p][1] = 0ull; }

        #pragma unroll 4
        for (int k = 0; k < 128; k++) {
            float2 wv = *(float2*)&sWba[k * 128 + jb];
            unsigned long long w0 = dup2(wv.x), w1 = dup2(wv.y);
            ulonglong2 mA = *(ulonglong2*)&sMT[k * 64 + eb];
            ulonglong2 mB = *(ulonglong2*)&sMT[k * 64 + eb + 4];
            FMA2(acc[0][0], mA.x, w0); FMA2(acc[0][1], mA.x, w1);
            FMA2(acc[1][0], mA.y, w0); FMA2(acc[1][1], mA.y, w1);
            FMA2(acc[2][0], mB.x, w0); FMA2(acc[2][1], mB.x, w1);
            FMA2(acc[3][0], mB.y, w0); FMA2(acc[3][1], mB.y, w1);
        }

        // rbf modulation: rw = rbf @ W_rbf
        unsigned long long rw[4][2];
        #pragma unroll
        for (int p = 0; p < 4; p++) { rw[p][0] = 0ull; rw[p][1] = 0ull; }
        #pragma unroll
        for (int s = 0; s < 16; s++) {
            float2 wv = *(float2*)&sWrbf[s * 128 + jb];
            unsigned long long w0 = dup2(wv.x), w1 = dup2(wv.y);
            ulonglong2 rA = *(ulonglong2*)&sRbfT[s * 64 + eb];
            ulonglong2 rB = *(ulonglong2*)&sRbfT[s * 64 + eb + 4];
            FMA2(rw[0][0], rA.x, w0); FMA2(rw[0][1], rA.x, w1);
            FMA2(rw[1][0], rA.y, w0); FMA2(rw[1][1], rA.y, w1);
            FMA2(rw[2][0], rB.x, w0); FMA2(rw[2][1], rB.x, w1);
            FMA2(rw[3][0], rB.y, w0); FMA2(rw[3][1], rB.y, w1);
        }

        __syncthreads();   // all reads of sMT/sRbfT done; region becomes sXT

        // x = ssilu(acc)*rw, store transposed [j][e] (stride 66)
        #pragma unroll
        for (int p = 0; p < 4; p++) {
            #pragma unroll
            for (int c = 0; c < 2; c++) {
                float a0, a1, r0, r1;
                up2(a0, a1, acc[p][c]);
                up2(r0, r1, rw[p][c]);
                float x0 = ssilu(a0) * r0, x1 = ssilu(a1) * r1;
                *(unsigned long long*)&sXT[(jb + c) * 66 + eb + 2 * p] = pk2(x0, x1);
            }
        }
        __syncthreads();

        // down projection: thread (pd_p, pd_d): full dot over 128 j
        unsigned long long s2 = 0ull;
        #pragma unroll 8
        for (int j = 0; j < 128; j++) {
            unsigned long long xv = *(unsigned long long*)&sXT[j * 66 + pd_p * 2];
            unsigned long long wv = dup2(sWd[j * 16 + pd_d]);
            FMA2(s2, xv, wv);
        }
        float v0, v1;
        up2(v0, v1, s2);
        int ea = e0 + pd_p * 2;
        if (ea < E)     g_xdown[(size_t)ea * 16 + pd_d] = v0;
        if (ea + 1 < E) g_xdown[(size_t)(ea + 1) * 16 + pd_d] = v1;
    }
}

// ---------------- K2: triplet gather/modulate/scatter (FFMA2) -------------
__global__ __launch_bounds__(256) void k_triplet(
    const float* __restrict__ cbf,
    const int* __restrict__ ba, const int* __restrict__ ca,
    const float* __restrict__ Wcbf, int T)
{
    __shared__ __align__(16) float sW[256];   // [s][d]
    int tid = threadIdx.x;
    sW[tid] = Wcbf[tid];
    __syncthreads();

    int t = blockIdx.x * 256 + tid;
    if (t >= T) return;

    float cv[16];
    {
        const float4* cp = (const float4*)(cbf + (size_t)t * 16);
        float4 a = cp[0], b = cp[1], c = cp[2], d = cp[3];
        cv[0]=a.x; cv[1]=a.y; cv[2]=a.z; cv[3]=a.w;
        cv[4]=b.x; cv[5]=b.y; cv[6]=b.z; cv[7]=b.w;
        cv[8]=c.x; cv[9]=c.y; cv[10]=c.z; cv[11]=c.w;
        cv[12]=d.x; cv[13]=d.y; cv[14]=d.z; cv[15]=d.w;
    }

    unsigned long long o2[8];
    #pragma unroll
    for (int q = 0; q < 8; q++) o2[q] = 0ull;
    #pragma unroll
    for (int s = 0; s < 16; s++) {
        unsigned long long cd = dup2(cv[s]);
        ulonglong2 wA = *(ulonglong2*)&sW[s * 16];
        ulonglong2 wB = *(ulonglong2*)&sW[s * 16 + 4];
        ulonglong2 wC = *(ulonglong2*)&sW[s * 16 + 8];
        ulonglong2 wD = *(ulonglong2*)&sW[s * 16 + 12];
        FMA2(o2[0], cd, wA.x); FMA2(o2[1], cd, wA.y);
        FMA2(o2[2], cd, wB.x); FMA2(o2[3], cd, wB.y);
        FMA2(o2[4], cd, wC.x); FMA2(o2[5], cd, wC.y);
        FMA2(o2[6], cd, wD.x); FMA2(o2[7], cd, wD.y);
    }

    int b = ba[t], a = ca[t];
    const ulonglong2* xd = (const ulonglong2*)(g_xdown + (size_t)b * 16);
    float* dst = g_xe + (size_t)a * 16;
    ulonglong2 x01 = xd[0], x23 = xd[1], x45 = xd[2], x67 = xd[3];
    unsigned long long p0, p1;
    float v0, v1, v2, v3;

    MUL2(p0, o2[0], x01.x); MUL2(p1, o2[1], x01.y);
    up2(v0, v1, p0); up2(v2, v3, p1);
    asm volatile("red.global.add.v4.f32 [%0], {%1,%2,%3,%4};"
                 :: "l"(dst), "f"(v0), "f"(v1), "f"(v2), "f"(v3) : "memory");
    MUL2(p0, o2[2], x23.x); MUL2(p1, o2[3], x23.y);
    up2(v0, v1, p0); up2(v2, v3, p1);
    asm volatile("red.global.add.v4.f32 [%0], {%1,%2,%3,%4};"
                 :: "l"(dst + 4), "f"(v0), "f"(v1), "f"(v2), "f"(v3) : "memory");
    MUL2(p0, o2[4], x45.x); MUL2(p1, o2[5], x45.y);
    up2(v0, v1, p0); up2(v2, v3, p1);
    asm volatile("red.global.add.v4.f32 [%0], {%1,%2,%3,%4};"
                 :: "l"(dst + 8), "f"(v0), "f"(v1), "f"(v2), "f"(v3) : "memory");
    MUL2(p0, o2[6], x67.x); MUL2(p1, o2[7], x67.y);
    up2(v0, v1, p0); up2(v2, v3, p1);
    asm volatile("red.global.add.v4.f32 [%0], {%1,%2,%3,%4};"
                 :: "l"(dst + 12), "f"(v0), "f"(v1), "f"(v2), "f"(v3) : "memory");
}

// ---------------- K3: edge up-projection + atom scatter ----------
__global__ __launch_bounds__(256, 4) void k_edge_up(
    const float* __restrict__ m, const float* __restrict__ rbf,
    const int* __restrict__ idxt,
    const float* __restrict__ Wup, const float* __restrict__ Wra, int E)
{
    __shared__ __align__(16) float sWup[2048];   // [d][j]
    __shared__ __align__(16) float sWra[2048];   // [s][j]
    __shared__ __align__(16) float sXe[256];     // [16][16]
    __shared__ __align__(16) float sRb[256];     // [16][16]
    __shared__ int sIdx[16];

    int tid = threadIdx.x;
    for (int i = tid; i < 2048; i += 256) { sWup[i] = Wup[i]; sWra[i] = Wra[i]; }

    int lane = tid & 31, et = tid >> 5;
    int jb = lane * 4;
    int ntiles = (E + 15) >> 4;

    for (int tile = blockIdx.x; tile < ntiles; tile += gridDim.x) {
        int e0 = tile << 4;
        __syncthreads();
        if (tid < 64) {
            int e = tid >> 2, q = tid & 3;
            float4 vx = make_float4(0.f, 0.f, 0.f, 0.f), vr = vx;
            if (e0 + e < E) {
                vx = *(const float4*)(g_xe + (size_t)(e0 + e) * 16 + q * 4);
                vr = *(const float4*)(rbf + (size_t)(e0 + e) * 16 + q * 4);
            }
            *(float4*)&sXe[e * 16 + q * 4] = vx;
            *(float4*)&sRb[e * 16 + q * 4] = vr;
        }
        if (tid < 16) sIdx[tid] = (e0 + tid < E) ? idxt[e0 + tid] : -1;
        __syncthreads();

        unsigned long long u2[2][2], rr2[2][2];
        u2[0][0]=u2[0][1]=u2[1][0]=u2[1][1]=0ull;
        rr2[0][0]=rr2[0][1]=rr2[1][0]=rr2[1][1]=0ull;
        #pragma unroll
        for (int d = 0; d < 16; d++) {
            ulonglong2 wu = *(ulonglong2*)&sWup[d * 128 + jb];
            ulonglong2 wr = *(ulonglong2*)&sWra[d * 128 + jb];
            #pragma unroll
            for (int i = 0; i < 2; i++) {
                int e = et * 2 + i;
                unsigned long long xd = dup2(sXe[e * 16 + d]);
                unsigned long long rd = dup2(sRb[e * 16 + d]);
                FMA2(u2[i][0], xd, wu.x);  FMA2(u2[i][1], xd, wu.y);
                FMA2(rr2[i][0], rd, wr.x); FMA2(rr2[i][1], rd, wr.y);
            }
        }
        #pragma unroll
        for (int i = 0; i < 2; i++) {
            int e = et * 2 + i;
            int a = sIdx[e];
            if (a < 0) continue;
            float4 mm = *(const float4*)(m + (size_t)(e0 + e) * 128 + jb);
            float ua, ub, uc, ud, ra, rb, rc, rd;
            up2(ua, ub, u2[i][0]); up2(uc, ud, u2[i][1]);
            up2(ra, rb, rr2[i][0]); up2(rc, rd, rr2[i][1]);
            float vx = (mm.x + ssilu(ua)) * ra;
            float vy = (mm.y + ssilu(ub)) * rb;
            float vz = (mm.z + ssilu(uc)) * rc;
            float vw = (mm.w + ssilu(ud)) * rd;
            float* dst = g_h + (size_t)a * 128 + jb;
            asm volatile("red.global.add.v4.f32 [%0], {%1,%2,%3,%4};"
                         :: "l"(dst), "f"(vx), "f"(vy), "f"(vz), "f"(vw)
                         : "memory");
        }
    }
}

// ---------------- K4: atom output GEMM ----------------
__global__ __launch_bounds__(256, 2) void k_atom_out(
    const float* __restrict__ Watom, float* __restrict__ out, int N)
{
    extern __shared__ float sm_[];
    float* sW = sm_;             // 16384 [k][j]
    float* sH = sm_ + 16384;     // 32*132

    int tid = threadIdx.x;
    for (int i = tid; i < 16384; i += 256) sW[i] = Watom[i];

    int ntiles = (N + 31) >> 5;
    int jt = tid & 31, et = tid >> 5;

    for (int tile = blockIdx.x; tile < ntiles; tile += gridDim.x) {
        int r0 = tile << 5;
        __syncthreads();
        for (int r = tid; r < 1024; r += 256) {
            int e = r >> 5, c = r & 31;
            float4 v = make_float4(0.f, 0.f, 0.f, 0.f);
            if (r0 + e < N) v = ((const float4*)(g_h + (size_t)(r0 + e) * 128))[c];
            *((float4*)&sH[e * 132 + c * 4]) = v;
        }
        __syncthreads();

        float acc[4][4];
        #pragma unroll
        for (int i = 0; i < 4; i++) {
            acc[i][0] = 0.f; acc[i][1] = 0.f; acc[i][2] = 0.f; acc[i][3] = 0.f;
        }
        #pragma unroll 4
        for (int k4 = 0; k4 < 32; k4++) {
            float4 mv[4];
            #pragma unroll
            for (int i = 0; i < 4; i++)
                mv[i] = *((float4*)&sH[(et * 4 + i) * 132 + k4 * 4]);
            #pragma unroll
            for (int kk = 0; kk < 4; kk++) {
                float4 w = *((float4*)&sW[(k4 * 4 + kk) * 128 + jt * 4]);
                #pragma unroll
                for (int i = 0; i < 4; i++) {
                    float mk = (kk == 0) ? mv[i].x : (kk == 1) ? mv[i].y
                             : (kk == 2) ? mv[i].z : mv[i].w;
                    acc[i][0] += mk * w.x;
                    acc[i][1] += mk * w.y;
                    acc[i][2] += mk * w.z;
                    acc[i][3] += mk * w.w;
                }
            }
        }
        #pragma unroll
        for (int i = 0; i < 4; i++) {
            int rrow = r0 + et * 4 + i;
            if (rrow < N) {
                float4 v;
                v.x = ssilu(acc[i][0]);
                v.y = ssilu(acc[i][1]);
                v.z = ssilu(acc[i][2]);
                v.w = ssilu(acc[i][3]);
                *((float4*)(out + (size_t)rrow * 128 + jt * 4)) = v;
            }
        }
        __syncthreads();
    }
}

extern "C" void kernel_launch(void* const* d_in, const int* in_sizes, int n_in,
                              void* d_out, int out_size) {
    const float* m     = (const float*)d_in[0];
    const float* rbf   = (const float*)d_in[1];
    const float* cbf   = (const float*)d_in[2];
    const int*   id3ba = (const int*)d_in[3];
    const int*   id3ca = (const int*)d_in[4];
    const int*   idxt  = (const int*)d_in[5];
    const float* Wba   = (const float*)d_in[6];
    const float* Wrbf  = (const float*)d_in[7];
    const float* Wdown = (const float*)d_in[8];
    const float* Wcbf  = (const float*)d_in[9];
    const float* Wup   = (const float*)d_in[10];
    const float* Wra   = (const float*)d_in[11];
    const float* Watom = (const float*)d_in[12];

    int E = in_sizes[0] / 128;
    int T = in_sizes[2] / 16;
    int N = out_size / 128;

    // smem: Wba 16384 + Wrbf 2048 + Wd 2048 + max(sMT 8192 + sRbfT 1024, sXT 128*66)
    const int k1_smem = (16384 + 2048 + 2048 + 9216) * 4;
    const int k4_smem = (16384 + 32 * 132) * 4;
    cudaFuncSetAttribute(k_edge_down, cudaFuncAttributeMaxDynamicSharedMemorySize, k1_smem);
    cudaFuncSetAttribute(k_atom_out, cudaFuncAttributeMaxDynamicSharedMemorySize, k4_smem);

    k_zero<<<512, 256>>>((E * 16) / 4, (N * 128) / 4);
    k_edge_down<<<148, 512, k1_smem>>>(m, rbf, Wba, Wrbf, Wdown, E);
    k_triplet<<<(T + 255) / 256, 256>>>(cbf, id3ba, id3ca, Wcbf, T);
    k_edge_up<<<4096, 256>>>(m, rbf, idxt, Wup, Wra, E);
    k_atom_out<<<(N + 31) / 32, 256, k4_smem>>>(Watom, (float*)d_out, N);
}

// round 5
// speedup vs baseline: 1.4739x; 1.4739x over previous
#include <cuda_runtime.h>
#include <cstdint>

#define SSCALE 1.6666666666666667f

__device__ __forceinline__ float ssilu(float x) {
    float e = __expf(-x);
    return SSCALE * __fdividef(x, 1.0f + e);
}

// ---- packed f32x2 helpers ----
__device__ __forceinline__ unsigned long long dup2(float x) {
    unsigned long long r;
    asm("mov.b64 %0, {%1, %1};" : "=l"(r) : "f"(x));
    return r;
}
__device__ __forceinline__ void up2(float& x, float& y, unsigned long long v) {
    asm("mov.b64 {%0, %1}, %2;" : "=f"(x), "=f"(y) : "l"(v));
}
#define FMA2(d, a, b) asm("fma.rn.f32x2 %0, %1, %2, %0;" : "+l"(d) : "l"(a), "l"(b))
#define MUL2(d, a, b) asm("mul.rn.f32x2 %0, %1, %2;" : "=l"(d) : "l"(a), "l"(b))

// ---- bf16 split + mma helpers ----
__device__ __forceinline__ void split2(float v0, float v1, uint32_t& hi, uint32_t& lo) {
    asm("cvt.rn.bf16x2.f32 %0, %1, %2;" : "=r"(hi) : "f"(v1), "f"(v0));
    float h0 = __uint_as_float(hi << 16);
    float h1 = __uint_as_float(hi & 0xFFFF0000u);
    float r0 = v0 - h0, r1 = v1 - h1;
    asm("cvt.rn.bf16x2.f32 %0, %1, %2;" : "=r"(lo) : "f"(r1), "f"(r0));
}
__device__ __forceinline__ void mma_bf16(float* d, uint32_t a0, uint32_t a1,
                                         uint32_t a2, uint32_t a3,
                                         uint32_t b0, uint32_t b1) {
    asm("mma.sync.aligned.m16n8k16.row.col.f32.bf16.bf16.f32 "
        "{%0,%1,%2,%3}, {%4,%5,%6,%7}, {%8,%9}, {%0,%1,%2,%3};"
        : "+f"(d[0]), "+f"(d[1]), "+f"(d[2]), "+f"(d[3])
        : "r"(a0), "r"(a1), "r"(a2), "r"(a3), "r"(b0), "r"(b1));
}
#define LDSM4(d0, d1, d2, d3, a) asm volatile( \
    "ldmatrix.sync.aligned.m8n8.x4.shared.b16 {%0,%1,%2,%3}, [%4];" \
    : "=r"(d0), "=r"(d1), "=r"(d2), "=r"(d3) : "r"(a))
#define LDSM4T(d0, d1, d2, d3, a) asm volatile( \
    "ldmatrix.sync.aligned.m8n8.x4.trans.shared.b16 {%0,%1,%2,%3}, [%4];" \
    : "=r"(d0), "=r"(d1), "=r"(d2), "=r"(d3) : "r"(a))

__device__ __forceinline__ uint32_t smem_u32(const void* p) {
    uint32_t a;
    asm("{ .reg .u64 t; cvta.to.shared.u64 t, %1; cvt.u32.u64 %0, t; }"
        : "=r"(a) : "l"(p));
    return a;
}

#define E_MAX 700000
#define N_MAX 40000

__device__ __align__(16) float g_xdown[(size_t)E_MAX * 16];
__device__ __align__(16) float g_xe[(size_t)E_MAX * 16];
__device__ __align__(16) float g_h[(size_t)N_MAX * 128];

// ---------------- K0: zero scratch ----------------
__global__ void k_zero(int n_xe4, int n_h4) {
    int i = blockIdx.x * blockDim.x + threadIdx.x;
    int stride = gridDim.x * blockDim.x;
    float4 z = make_float4(0.f, 0.f, 0.f, 0.f);
    for (int r = i; r < n_xe4; r += stride) ((float4*)g_xe)[r] = z;
    for (int r = i; r < n_h4; r += stride) ((float4*)g_h)[r] = z;
}

// ---------------- K1: edge dense + down projection (HMMA) -----------------
// x_ba = ssilu(m @ W_ba) * (rbf @ W_rbf);  g_xdown = x_ba @ W_down
// 64 edges/tile; 8 warps = 4 row-blocks x 2 col-halves; split-bf16 3-pass.
// smem byte offsets (dynamic):
//  BH 0, BL 34816, WRH 69632, WRL 73984, WD 78336 (fp32 [16][132]),
//  AH 86784, AL 104192, RBH 121600, RBL 124672, end 127744.
//  X (fp32 [64][132]) aliases AH/AL at 86784.
#define OFF_BH  0
#define OFF_BL  34816
#define OFF_WRH 69632
#define OFF_WRL 73984
#define OFF_WD  78336
#define OFF_AH  86784
#define OFF_AL  104192
#define OFF_RBH 121600
#define OFF_RBL 124672
#define K1_SMEM 127744

__global__ __launch_bounds__(256, 1) void k_edge_down_hmma(
    const float* __restrict__ m, const float* __restrict__ rbf,
    const float* __restrict__ Wba, const float* __restrict__ Wrbf,
    const float* __restrict__ Wdown, int E)
{
    extern __shared__ char smem[];
    uint32_t sb = smem_u32(smem);
    int tid = threadIdx.x;
    int l = tid & 31, w = tid >> 5;

    // ---- one-time weight conversion ----
    // W_ba [128k][128n] -> hi/lo bf16, stride 136 b16 (272 B)
    for (int i = tid; i < 8192; i += 256) {
        int k = i >> 6, n = (i & 63) * 2;
        float v0 = Wba[(size_t)k * 128 + n];
        float v1 = Wba[(size_t)k * 128 + n + 1];
        uint32_t hp, lp;
        split2(v0, v1, hp, lp);
        *(uint32_t*)(smem + OFF_BH + k * 272 + n * 2) = hp;
        *(uint32_t*)(smem + OFF_BL + k * 272 + n * 2) = lp;
    }
    // W_rbf [16k][128n]
    for (int i = tid; i < 1024; i += 256) {
        int k = i >> 6, n = (i & 63) * 2;
        float v0 = Wrbf[(size_t)k * 128 + n];
        float v1 = Wrbf[(size_t)k * 128 + n + 1];
        uint32_t hp, lp;
        split2(v0, v1, hp, lp);
        *(uint32_t*)(smem + OFF_WRH + k * 272 + n * 2) = hp;
        *(uint32_t*)(smem + OFF_WRL + k * 272 + n * 2) = lp;
    }
    // W_down transposed fp32 [16][132]
    float* sWdT = (float*)(smem + OFF_WD);
    for (int i = tid; i < 2048; i += 256) {
        int d = i >> 7, j = i & 127;
        sWdT[d * 132 + j] = Wdown[(size_t)j * 16 + d];
    }

    // ---- per-lane ldmatrix addresses ----
    int rowm = (l < 16) ? l : (l - 16);
    int colo = (l < 16) ? 0 : 8;
    int rb = w & 3, ch = w >> 2;

    uint32_t aH = sb + OFF_AH + (rb * 16 + rowm) * 272 + colo * 2;
    uint32_t aL = aH + (OFF_AL - OFF_AH);
    uint32_t rH = sb + OFF_RBH + (rb * 16 + rowm) * 48 + colo * 2;
    uint32_t rL = rH + (OFF_RBL - OFF_RBH);
    uint32_t bH = sb + OFF_BH + rowm * 272 + (ch * 64 + colo) * 2;
    uint32_t bL = bH + (OFF_BL - OFF_BH);
    uint32_t wrH = sb + OFF_WRH + rowm * 272 + (ch * 64 + colo) * 2;
    uint32_t wrL = wrH + (OFF_WRL - OFF_WRH);

    float* sX = (float*)(smem + OFF_AH);

    int ntiles = (E + 63) >> 6;
    for (int tile = blockIdx.x; tile < ntiles; tile += gridDim.x) {
        int e0 = tile << 6;
        __syncthreads();   // prev down-proj reads done / weights ready

        // ---- convert m tile [64][128] -> sAH/sAL ----
        #pragma unroll 4
        for (int it = 0; it < 8; it++) {
            int r = tid + it * 256;
            int e = r >> 5, kq = r & 31;
            float4 v = make_float4(0.f, 0.f, 0.f, 0.f);
            if (e0 + e < E) v = *(const float4*)(m + (size_t)(e0 + e) * 128 + kq * 4);
            uint32_t h01, l01, h23, l23;
            split2(v.x, v.y, h01, l01);
            split2(v.z, v.w, h23, l23);
            unsigned long long hh = ((unsigned long long)h23 << 32) | h01;
            unsigned long long ll = ((unsigned long long)l23 << 32) | l01;
            *(unsigned long long*)(smem + OFF_AH + e * 272 + kq * 8) = hh;
            *(unsigned long long*)(smem + OFF_AL + e * 272 + kq * 8) = ll;
        }
        // ---- convert rbf tile [64][16] -> sRbH/sRbL (stride 24 b16) ----
        {
            int e = tid >> 2, kp = tid & 3;   // 256 threads: 64 e x 4 pairs... need 8 pairs
            #pragma unroll
            for (int half = 0; half < 2; half++) {
                int k = (kp + half * 4) * 2;
                float2 v = make_float2(0.f, 0.f);
                if (e0 + e < E) v = *(const float2*)(rbf + (size_t)(e0 + e) * 16 + k);
                uint32_t hp, lp;
                split2(v.x, v.y, hp, lp);
                *(uint32_t*)(smem + OFF_RBH + e * 48 + k * 2) = hp;
                *(uint32_t*)(smem + OFF_RBL + e * 48 + k * 2) = lp;
            }
        }
        __syncthreads();

        // ---- rw = rbf @ W_rbf (one k-step, 3-pass) ----
        float rw[8][4];
        #pragma unroll
        for (int t = 0; t < 8; t++) {
            rw[t][0] = 0.f; rw[t][1] = 0.f; rw[t][2] = 0.f; rw[t][3] = 0.f;
        }
        {
            uint32_t ra0, ra1, ra2, ra3, rl0, rl1, rl2, rl3;
            LDSM4(ra0, ra1, ra2, ra3, rH);
            LDSM4(rl0, rl1, rl2, rl3, rL);
            #pragma unroll
            for (int p = 0; p < 4; p++) {
                uint32_t b0, b1, b2, b3, c0, c1, c2, c3;
                LDSM4T(b0, b1, b2, b3, wrH + p * 32);
                LDSM4T(c0, c1, c2, c3, wrL + p * 32);
                mma_bf16(rw[p * 2], ra0, ra1, ra2, ra3, b0, b1);
                mma_bf16(rw[p * 2], rl0, rl1, rl2, rl3, b0, b1);
                mma_bf16(rw[p * 2], ra0, ra1, ra2, ra3, c0, c1);
                mma_bf16(rw[p * 2 + 1], ra0, ra1, ra2, ra3, b2, b3);
                mma_bf16(rw[p * 2 + 1], rl0, rl1, rl2, rl3, b2, b3);
                mma_bf16(rw[p * 2 + 1], ra0, ra1, ra2, ra3, c2, c3);
            }
        }

        // ---- main GEMM: m @ W_ba, 8 k-steps, 3-pass ----
        float acc[8][4];
        #pragma unroll
        for (int t = 0; t < 8; t++) {
            acc[t][0] = 0.f; acc[t][1] = 0.f; acc[t][2] = 0.f; acc[t][3] = 0.f;
        }
        #pragma unroll
        for (int ks = 0; ks < 8; ks++) {
            uint32_t ah0, ah1, ah2, ah3, al0, al1, al2, al3;
            LDSM4(ah0, ah1, ah2, ah3, aH + ks * 32);
            LDSM4(al0, al1, al2, al3, aL + ks * 32);
            uint32_t bkb = bH + ks * 16 * 272;
            uint32_t lkb = bL + ks * 16 * 272;
            #pragma unroll
            for (int p = 0; p < 4; p++) {
                uint32_t b0, b1, b2, b3, c0, c1, c2, c3;
                LDSM4T(b0, b1, b2, b3, bkb + p * 32);
                LDSM4T(c0, c1, c2, c3, lkb + p * 32);
                mma_bf16(acc[p * 2], ah0, ah1, ah2, ah3, b0, b1);
                mma_bf16(acc[p * 2], al0, al1, al2, al3, b0, b1);
                mma_bf16(acc[p * 2], ah0, ah1, ah2, ah3, c0, c1);
                mma_bf16(acc[p * 2 + 1], ah0, ah1, ah2, ah3, b2, b3);
                mma_bf16(acc[p * 2 + 1], al0, al1, al2, al3, b2, b3);
                mma_bf16(acc[p * 2 + 1], ah0, ah1, ah2, ah3, c2, c3);
            }
        }

        __syncthreads();   // all A reads done; region becomes sX

        // ---- epilogue: x = ssilu(acc) * rw -> sX [64][132] fp32 ----
        {
            int r_ = l >> 2, c2 = (l & 3) * 2;
            int row0 = rb * 16 + r_;
            #pragma unroll
            for (int t = 0; t < 8; t++) {
                int col = ch * 64 + t * 8 + c2;
                float x0 = ssilu(acc[t][0]) * rw[t][0];
                float x1 = ssilu(acc[t][1]) * rw[t][1];
                float x2 = ssilu(acc[t][2]) * rw[t][2];
                float x3 = ssilu(acc[t][3]) * rw[t][3];
                *(float2*)&sX[row0 * 132 + col] = make_float2(x0, x1);
                *(float2*)&sX[(row0 + 8) * 132 + col] = make_float2(x2, x3);
            }
        }
        __syncthreads();

        // ---- down projection (R2 scheme): 64e x 16d ----
        for (int o = tid; o < 1024; o += 256) {
            int e = o >> 4, d = o & 15;
            unsigned long long s0 = 0ull, s1 = 0ull;
            #pragma unroll
            for (int j8 = 0; j8 < 16; j8++) {
                ulonglong2 xA = *(ulonglong2*)&sX[e * 132 + j8 * 8];
                ulonglong2 xB = *(ulonglong2*)&sX[e * 132 + j8 * 8 + 4];
                ulonglong2 wA = *(ulonglong2*)&sWdT[d * 132 + j8 * 8];
                ulonglong2 wB = *(ulonglong2*)&sWdT[d * 132 + j8 * 8 + 4];
                FMA2(s0, xA.x, wA.x); FMA2(s1, xA.y, wA.y);
                FMA2(s0, xB.x, wB.x); FMA2(s1, xB.y, wB.y);
            }
            float a, b, c, dd;
            up2(a, b, s0); up2(c, dd, s1);
            if (e0 + e < E) g_xdown[(size_t)(e0 + e) * 16 + d] = (a + b) + (c + dd);
        }
    }
}

// ---------------- K2: triplet gather/modulate/scatter (FFMA2) -------------
__global__ __launch_bounds__(256) void k_triplet(
    const float* __restrict__ cbf,
    const int* __restrict__ ba, const int* __restrict__ ca,
    const float* __restrict__ Wcbf, int T)
{
    __shared__ __align__(16) float sW[256];   // [s][d]
    int tid = threadIdx.x;
    sW[tid] = Wcbf[tid];
    __syncthreads();

    int t = blockIdx.x * 256 + tid;
    if (t >= T) return;

    float cv[16];
    {
        const float4* cp = (const float4*)(cbf + (size_t)t * 16);
        float4 a = cp[0], b = cp[1], c = cp[2], d = cp[3];
        cv[0]=a.x; cv[1]=a.y; cv[2]=a.z; cv[3]=a.w;
        cv[4]=b.x; cv[5]=b.y; cv[6]=b.z; cv[7]=b.w;
        cv[8]=c.x; cv[9]=c.y; cv[10]=c.z; cv[11]=c.w;
        cv[12]=d.x; cv[13]=d.y; cv[14]=d.z; cv[15]=d.w;
    }

    unsigned long long o2[8];
    #pragma unroll
    for (int q = 0; q < 8; q++) o2[q] = 0ull;
    #pragma unroll
    for (int s = 0; s < 16; s++) {
        unsigned long long cd = dup2(cv[s]);
        ulonglong2 wA = *(ulonglong2*)&sW[s * 16];
        ulonglong2 wB = *(ulonglong2*)&sW[s * 16 + 4];
        ulonglong2 wC = *(ulonglong2*)&sW[s * 16 + 8];
        ulonglong2 wD = *(ulonglong2*)&sW[s * 16 + 12];
        FMA2(o2[0], cd, wA.x); FMA2(o2[1], cd, wA.y);
        FMA2(o2[2], cd, wB.x); FMA2(o2[3], cd, wB.y);
        FMA2(o2[4], cd, wC.x); FMA2(o2[5], cd, wC.y);
        FMA2(o2[6], cd, wD.x); FMA2(o2[7], cd, wD.y);
    }

    int b = ba[t], a = ca[t];
    const ulonglong2* xd = (const ulonglong2*)(g_xdown + (size_t)b * 16);
    float* dst = g_xe + (size_t)a * 16;
    ulonglong2 x01 = xd[0], x23 = xd[1], x45 = xd[2], x67 = xd[3];
    unsigned long long p0, p1;
    float v0, v1, v2, v3;

    MUL2(p0, o2[0], x01.x); MUL2(p1, o2[1], x01.y);
    up2(v0, v1, p0); up2(v2, v3, p1);
    asm volatile("red.global.add.v4.f32 [%0], {%1,%2,%3,%4};"
                 :: "l"(dst), "f"(v0), "f"(v1), "f"(v2), "f"(v3) : "memory");
    MUL2(p0, o2[2], x23.x); MUL2(p1, o2[3], x23.y);
    up2(v0, v1, p0); up2(v2, v3, p1);
    asm volatile("red.global.add.v4.f32 [%0], {%1,%2,%3,%4};"
                 :: "l"(dst + 4), "f"(v0), "f"(v1), "f"(v2), "f"(v3) : "memory");
    MUL2(p0, o2[4], x45.x); MUL2(p1, o2[5], x45.y);
    up2(v0, v1, p0); up2(v2, v3, p1);
    asm volatile("red.global.add.v4.f32 [%0], {%1,%2,%3,%4};"
                 :: "l"(dst + 8), "f"(v0), "f"(v1), "f"(v2), "f"(v3) : "memory");
    MUL2(p0, o2[6], x67.x); MUL2(p1, o2[7], x67.y);
    up2(v0, v1, p0); up2(v2, v3, p1);
    asm volatile("red.global.add.v4.f32 [%0], {%1,%2,%3,%4};"
                 :: "l"(dst + 12), "f"(v0), "f"(v1), "f"(v2), "f"(v3) : "memory");
}

// ---------------- K3: edge up-projection + atom scatter ----------
__global__ __launch_bounds__(256, 4) void k_edge_up(
    const float* __restrict__ m, const float* __restrict__ rbf,
    const int* __restrict__ idxt,
    const float* __restrict__ Wup, const float* __restrict__ Wra, int E)
{
    __shared__ __align__(16) float sWup[2048];   // [d][j]
    __shared__ __align__(16) float sWra[2048];   // [s][j]
    __shared__ __align__(16) float sXe[256];     // [16][16]
    __shared__ __align__(16) float sRb[256];     // [16][16]
    __shared__ int sIdx[16];

    int tid = threadIdx.x;
    for (int i = tid; i < 2048; i += 256) { sWup[i] = Wup[i]; sWra[i] = Wra[i]; }

    int lane = tid & 31, et = tid >> 5;
    int jb = lane * 4;
    int ntiles = (E + 15) >> 4;

    for (int tile = blockIdx.x; tile < ntiles; tile += gridDim.x) {
        int e0 = tile << 4;
        __syncthreads();
        if (tid < 64) {
            int e = tid >> 2, q = tid & 3;
            float4 vx = make_float4(0.f, 0.f, 0.f, 0.f), vr = vx;
            if (e0 + e < E) {
                vx = *(const float4*)(g_xe + (size_t)(e0 + e) * 16 + q * 4);
                vr = *(const float4*)(rbf + (size_t)(e0 + e) * 16 + q * 4);
            }
            *(float4*)&sXe[e * 16 + q * 4] = vx;
            *(float4*)&sRb[e * 16 + q * 4] = vr;
        }
        if (tid < 16) sIdx[tid] = (e0 + tid < E) ? idxt[e0 + tid] : -1;
        __syncthreads();

        unsigned long long u2[2][2], rr2[2][2];
        u2[0][0]=u2[0][1]=u2[1][0]=u2[1][1]=0ull;
        rr2[0][0]=rr2[0][1]=rr2[1][0]=rr2[1][1]=0ull;
        #pragma unroll
        for (int d = 0; d < 16; d++) {
            ulonglong2 wu = *(ulonglong2*)&sWup[d * 128 + jb];
            ulonglong2 wr = *(ulonglong2*)&sWra[d * 128 + jb];
            #pragma unroll
            for (int i = 0; i < 2; i++) {
                int e = et * 2 + i;
                unsigned long long xd = dup2(sXe[e * 16 + d]);
                unsigned long long rd = dup2(sRb[e * 16 + d]);
                FMA2(u2[i][0], xd, wu.x);  FMA2(u2[i][1], xd, wu.y);
                FMA2(rr2[i][0], rd, wr.x); FMA2(rr2[i][1], rd, wr.y);
            }
        }
        #pragma unroll
        for (int i = 0; i < 2; i++) {
            int e = et * 2 + i;
            int a = sIdx[e];
            if (a < 0) continue;
            float4 mm = *(const float4*)(m + (size_t)(e0 + e) * 128 + jb);
            float ua, ub, uc, ud, ra, rb, rc, rd;
            up2(ua, ub, u2[i][0]); up2(uc, ud, u2[i][1]);
            up2(ra, rb, rr2[i][0]); up2(rc, rd, rr2[i][1]);
            float vx = (mm.x + ssilu(ua)) * ra;
            float vy = (mm.y + ssilu(ub)) * rb;
            float vz = (mm.z + ssilu(uc)) * rc;
            float vw = (mm.w + ssilu(ud)) * rd;
            float* dst = g_h + (size_t)a * 128 + jb;
            asm volatile("red.global.add.v4.f32 [%0], {%1,%2,%3,%4};"
                         :: "l"(dst), "f"(vx), "f"(vy), "f"(vz), "f"(vw)
                         : "memory");
        }
    }
}

// ---------------- K4: atom output GEMM ----------------
__global__ __launch_bounds__(256, 2) void k_atom_out(
    const float* __restrict__ Watom, float* __restrict__ out, int N)
{
    extern __shared__ float sm_[];
    float* sW = sm_;             // 16384 [k][j]
    float* sH = sm_ + 16384;     // 32*132

    int tid = threadIdx.x;
    for (int i = tid; i < 16384; i += 256) sW[i] = Watom[i];

    int ntiles = (N + 31) >> 5;
    int jt = tid & 31, et = tid >> 5;

    for (int tile = blockIdx.x; tile < ntiles; tile += gridDim.x) {
        int r0 = tile << 5;
        __syncthreads();
        for (int r = tid; r < 1024; r += 256) {
            int e = r >> 5, c = r & 31;
            float4 v = make_float4(0.f, 0.f, 0.f, 0.f);
            if (r0 + e < N) v = ((const float4*)(g_h + (size_t)(r0 + e) * 128))[c];
            *((float4*)&sH[e * 132 + c * 4]) = v;
        }
        __syncthreads();

        float acc[4][4];
        #pragma unroll
        for (int i = 0; i < 4; i++) {
            acc[i][0] = 0.f; acc[i][1] = 0.f; acc[i][2] = 0.f; acc[i][3] = 0.f;
        }
        #pragma unroll 4
        for (int k4 = 0; k4 < 32; k4++) {
            float4 mv[4];
            #pragma unroll
            for (int i = 0; i < 4; i++)
                mv[i] = *((float4*)&sH[(et * 4 + i) * 132 + k4 * 4]);
            #pragma unroll
            for (int kk = 0; kk < 4; kk++) {
                float4 w = *((float4*)&sW[(k4 * 4 + kk) * 128 + jt * 4]);
                #pragma unroll
                for (int i = 0; i < 4; i++) {
                    float mk = (kk == 0) ? mv[i].x : (kk == 1) ? mv[i].y
                             : (kk == 2) ? mv[i].z : mv[i].w;
                    acc[i][0] += mk * w.x;
                    acc[i][1] += mk * w.y;
                    acc[i][2] += mk * w.z;
                    acc[i][3] += mk * w.w;
                }
            }
        }
        #pragma unroll
        for (int i = 0; i < 4; i++) {
            int rrow = r0 + et * 4 + i;
            if (rrow < N) {
                float4 v;
                v.x = ssilu(acc[i][0]);
                v.y = ssilu(acc[i][1]);
                v.z = ssilu(acc[i][2]);
                v.w = ssilu(acc[i][3]);
                *((float4*)(out + (size_t)rrow * 128 + jt * 4)) = v;
            }
        }
        __syncthreads();
    }
}

extern "C" void kernel_launch(void* const* d_in, const int* in_sizes, int n_in,
                              void* d_out, int out_size) {
    const float* m     = (const float*)d_in[0];
    const float* rbf   = (const float*)d_in[1];
    const float* cbf   = (const float*)d_in[2];
    const int*   id3ba = (const int*)d_in[3];
    const int*   id3ca = (const int*)d_in[4];
    const int*   idxt  = (const int*)d_in[5];
    const float* Wba   = (const float*)d_in[6];
    const float* Wrbf  = (const float*)d_in[7];
    const float* Wdown = (const float*)d_in[8];
    const float* Wcbf  = (const float*)d_in[9];
    const float* Wup   = (const float*)d_in[10];
    const float* Wra   = (const float*)d_in[11];
    const float* Watom = (const float*)d_in[12];

    int E = in_sizes[0] / 128;
    int T = in_sizes[2] / 16;
    int N = out_size / 128;

    const int k4_smem = (16384 + 32 * 132) * 4;
    cudaFuncSetAttribute(k_edge_down_hmma,
                         cudaFuncAttributeMaxDynamicSharedMemorySize, K1_SMEM);
    cudaFuncSetAttribute(k_atom_out,
                         cudaFuncAttributeMaxDynamicSharedMemorySize, k4_smem);

    k_zero<<<512, 256>>>((E * 16) / 4, (N * 128) / 4);
    k_edge_down_hmma<<<148, 256, K1_SMEM>>>(m, rbf, Wba, Wrbf, Wdown, E);
    k_triplet<<<(T + 255) / 256, 256>>>(cbf, id3ba, id3ca, Wcbf, T);
    k_edge_up<<<4096, 256>>>(m, rbf, idxt, Wup, Wra, E);
    k_atom_out<<<(N + 31) / 32, 256, k4_smem>>>(Watom, (float*)d_out, N);
}